// round 5
// baseline (speedup 1.0000x reference)
#include <cuda_runtime.h>
#include <math.h>

// Problem shape (fixed by reference)
#define NT    8192      // B*T tokens
#define HDIM  1024
#define FDIM  4096
#define NE    8
#define TOPK  2

// GEMM tiling
#define BM 128
#define BN 128
#define BK 8
#define BMP (BM + 4)    // padded lda for As

#define MAXPAIR (NT * TOPK + NE * BM)   // 17408 (segments padded to BM)
#define MTILES  (MAXPAIR / BM)          // 136

// ---------------------------------------------------------------------------
// Scratch (static .bss — no allocation)
// ---------------------------------------------------------------------------
__device__ int   g_counts[NE];
__device__ int   g_cursor[NE];
__device__ int   g_seg[NE + 1];
__device__ int   g_pair_token[MAXPAIR];
__device__ int   g_tok_e[NT * TOPK];
__device__ float g_tok_w[NT * TOPK];
__device__ int   g_tok_pair[NT * TOPK];
__device__ float g_hbuf[MAXPAIR * FDIM];   // intermediate relu(x@w1) per pair
__device__ float g_ybuf[MAXPAIR * HDIM];   // per-pair expert output

// ---------------------------------------------------------------------------
// Packed fp32x2 helpers (sm_103a)
// ---------------------------------------------------------------------------
__device__ __forceinline__ unsigned long long ffma2(unsigned long long a,
                                                    unsigned long long b,
                                                    unsigned long long c) {
    unsigned long long d;
    asm("fma.rn.f32x2 %0, %1, %2, %3;" : "=l"(d) : "l"(a), "l"(b), "l"(c));
    return d;
}
__device__ __forceinline__ unsigned long long pack2(float v) {
    unsigned long long d;
    asm("mov.b64 %0, {%1, %2};" : "=l"(d) : "f"(v), "f"(v));
    return d;
}
__device__ __forceinline__ float2 unpack2(unsigned long long v) {
    float2 r;
    asm("mov.b64 {%0, %1}, %2;" : "=f"(r.x), "=f"(r.y) : "l"(v));
    return r;
}

// ---------------------------------------------------------------------------
// Kernel 0: reset per-launch state (graph replays reuse state!)
// ---------------------------------------------------------------------------
__global__ void reset_kernel() {
    int id = blockIdx.x * blockDim.x + threadIdx.x;
    if (id < MAXPAIR) g_pair_token[id] = -1;
    if (id < NE) { g_counts[id] = 0; g_cursor[id] = 0; }
}

// ---------------------------------------------------------------------------
// Kernel 1: router — logits, top-2, softmax weights, expert counts
// One warp per token. gate_w transposed into smem for conflict-free reads.
// ---------------------------------------------------------------------------
__global__ void router_kernel(const float* __restrict__ x,
                              const float* __restrict__ gw,
                              float* __restrict__ logits_out,
                              int write_logits) {
    __shared__ float gwT[NE][HDIM];
    int tid = threadIdx.x;
    for (int idx = tid; idx < HDIM * NE; idx += 256) {
        int h = idx >> 3, e = idx & 7;
        gwT[e][h] = gw[idx];
    }
    __syncthreads();

    int warp = tid >> 5, lane = tid & 31;
    int t = blockIdx.x * 8 + warp;

    float acc[NE];
#pragma unroll
    for (int e = 0; e < NE; e++) acc[e] = 0.f;

    const float* xr = x + (size_t)t * HDIM;
    for (int i = lane; i < HDIM; i += 32) {
        float xv = xr[i];
#pragma unroll
        for (int e = 0; e < NE; e++) acc[e] += xv * gwT[e][i];
    }
#pragma unroll
    for (int e = 0; e < NE; e++)
        for (int off = 16; off; off >>= 1)
            acc[e] += __shfl_down_sync(0xffffffffu, acc[e], off);

    if (lane == 0) {
        if (write_logits) {
#pragma unroll
            for (int e = 0; e < NE; e++) logits_out[t * NE + e] = acc[e];
        }
        // top-2, jax tie semantics (strict >, ascending index)
        float l1 = -INFINITY, l2 = -INFINITY;
        int i1 = 0, i2 = 0;
#pragma unroll
        for (int e = 0; e < NE; e++) {
            float v = acc[e];
            if (v > l1)      { l2 = l1; i2 = i1; l1 = v; i1 = e; }
            else if (v > l2) { l2 = v; i2 = e; }
        }
        float b = expf(l2 - l1);
        float s = 1.f + b;
        g_tok_e[2 * t]     = i1;  g_tok_e[2 * t + 1] = i2;
        g_tok_w[2 * t]     = 1.f / s;
        g_tok_w[2 * t + 1] = b / s;
        atomicAdd(&g_counts[i1], 1);
        atomicAdd(&g_counts[i2], 1);
    }
}

// ---------------------------------------------------------------------------
// Kernel 2: segment scan (pad each expert segment to BM)
// ---------------------------------------------------------------------------
__global__ void scan_kernel() {
    int s = 0;
    for (int e = 0; e < NE; e++) {
        g_seg[e] = s;
        int c = g_counts[e];
        s += ((c + BM - 1) / BM) * BM;
    }
    g_seg[NE] = s;
}

// ---------------------------------------------------------------------------
// Kernel 3: assign pairs to expert-grouped slots
// ---------------------------------------------------------------------------
__global__ void assign_kernel() {
    int id = blockIdx.x * blockDim.x + threadIdx.x;
    if (id >= NT * TOPK) return;
    int e = g_tok_e[id];
    int pos = atomicAdd(&g_cursor[e], 1);
    int p = g_seg[e] + pos;
    g_pair_token[p] = id >> 1;
    g_tok_pair[id] = p;
}

// ---------------------------------------------------------------------------
// Kernel 4: GEMM1 — hbuf[p, :F] = relu( x[token(p), :H] @ w1[e] )
// 128x128x8 tiles, 256 threads, 8x8 microtile via fma.rn.f32x2
// ---------------------------------------------------------------------------
__global__ __launch_bounds__(256)
void ffn1_kernel(const float* __restrict__ x, const float* __restrict__ w1) {
    __shared__ __align__(16) float As[BK][BMP];
    __shared__ __align__(16) float Bs[BK][BN];

    int m0 = blockIdx.y * BM;
    if (m0 >= g_seg[NE]) return;
    int n0 = blockIdx.x * BN;

    int e = 0;
#pragma unroll
    for (int i = 0; i < NE; i++) if (m0 >= g_seg[i]) e = i;
    const float* W = w1 + (size_t)e * HDIM * FDIM;

    int tid = threadIdx.x;
    int ty = tid / 16, tx = tid % 16;

    // A-load mapping: 2 threads per row, 4 consecutive k each
    int am = tid >> 1, ak = (tid & 1) * 4;
    int tokA = g_pair_token[m0 + am];
    const float* aptr = (tokA >= 0) ? (x + (size_t)tokA * HDIM + ak) : 0;

    // B-load mapping: 32 threads per k-row, 4 consecutive n each
    int bk = tid >> 5, bn = (tid & 31) * 4;
    const float* bptr = W + (size_t)bk * FDIM + n0 + bn;

    unsigned long long c[8][4];
#pragma unroll
    for (int i = 0; i < 8; i++)
#pragma unroll
        for (int j = 0; j < 4; j++) c[i][j] = 0ull;

    for (int kt = 0; kt < HDIM; kt += BK) {
        float4 av = aptr ? *(const float4*)(aptr + kt)
                         : make_float4(0.f, 0.f, 0.f, 0.f);
        As[ak + 0][am] = av.x;
        As[ak + 1][am] = av.y;
        As[ak + 2][am] = av.z;
        As[ak + 3][am] = av.w;
        *(float4*)&Bs[bk][bn] = *(const float4*)(bptr + (size_t)kt * FDIM);
        __syncthreads();

#pragma unroll
        for (int k = 0; k < BK; k++) {
            float4 a0 = *(const float4*)&As[k][ty * 8];
            float4 a1 = *(const float4*)&As[k][ty * 8 + 4];
            float a[8] = {a0.x, a0.y, a0.z, a0.w, a1.x, a1.y, a1.z, a1.w};
            ulonglong2 b01 = *(const ulonglong2*)&Bs[k][tx * 8];
            ulonglong2 b23 = *(const ulonglong2*)&Bs[k][tx * 8 + 4];
            unsigned long long bb[4] = {b01.x, b01.y, b23.x, b23.y};
#pragma unroll
            for (int i = 0; i < 8; i++) {
                unsigned long long a2 = pack2(a[i]);
#pragma unroll
                for (int j = 0; j < 4; j++) c[i][j] = ffma2(a2, bb[j], c[i][j]);
            }
        }
        __syncthreads();
    }

    // epilogue: relu, store to hbuf
#pragma unroll
    for (int i = 0; i < 8; i++) {
        float2 v0 = unpack2(c[i][0]);
        float2 v1 = unpack2(c[i][1]);
        float2 v2 = unpack2(c[i][2]);
        float2 v3 = unpack2(c[i][3]);
        float4 r0 = make_float4(fmaxf(v0.x, 0.f), fmaxf(v0.y, 0.f),
                                fmaxf(v1.x, 0.f), fmaxf(v1.y, 0.f));
        float4 r1 = make_float4(fmaxf(v2.x, 0.f), fmaxf(v2.y, 0.f),
                                fmaxf(v3.x, 0.f), fmaxf(v3.y, 0.f));
        float* op = g_hbuf + (size_t)(m0 + ty * 8 + i) * FDIM + n0 + tx * 8;
        *(float4*)op = r0;
        *(float4*)(op + 4) = r1;
    }
}

// ---------------------------------------------------------------------------
// Kernel 5: GEMM2 — ybuf[p, :H] = hbuf[p, :F] @ w2[e]
// ---------------------------------------------------------------------------
__global__ __launch_bounds__(256)
void ffn2_kernel(const float* __restrict__ w2) {
    __shared__ __align__(16) float As[BK][BMP];
    __shared__ __align__(16) float Bs[BK][BN];

    int m0 = blockIdx.y * BM;
    if (m0 >= g_seg[NE]) return;
    int n0 = blockIdx.x * BN;

    int e = 0;
#pragma unroll
    for (int i = 0; i < NE; i++) if (m0 >= g_seg[i]) e = i;
    const float* W = w2 + (size_t)e * FDIM * HDIM;

    int tid = threadIdx.x;
    int ty = tid / 16, tx = tid % 16;

    int am = tid >> 1, ak = (tid & 1) * 4;
    const float* aptr = g_hbuf + (size_t)(m0 + am) * FDIM + ak;

    int bk = tid >> 5, bn = (tid & 31) * 4;
    const float* bptr = W + (size_t)bk * HDIM + n0 + bn;

    unsigned long long c[8][4];
#pragma unroll
    for (int i = 0; i < 8; i++)
#pragma unroll
        for (int j = 0; j < 4; j++) c[i][j] = 0ull;

    for (int kt = 0; kt < FDIM; kt += BK) {
        float4 av = *(const float4*)(aptr + kt);
        As[ak + 0][am] = av.x;
        As[ak + 1][am] = av.y;
        As[ak + 2][am] = av.z;
        As[ak + 3][am] = av.w;
        *(float4*)&Bs[bk][bn] = *(const float4*)(bptr + (size_t)kt * HDIM);
        __syncthreads();

#pragma unroll
        for (int k = 0; k < BK; k++) {
            float4 a0 = *(const float4*)&As[k][ty * 8];
            float4 a1 = *(const float4*)&As[k][ty * 8 + 4];
            float a[8] = {a0.x, a0.y, a0.z, a0.w, a1.x, a1.y, a1.z, a1.w};
            ulonglong2 b01 = *(const ulonglong2*)&Bs[k][tx * 8];
            ulonglong2 b23 = *(const ulonglong2*)&Bs[k][tx * 8 + 4];
            unsigned long long bb[4] = {b01.x, b01.y, b23.x, b23.y};
#pragma unroll
            for (int i = 0; i < 8; i++) {
                unsigned long long a2 = pack2(a[i]);
#pragma unroll
                for (int j = 0; j < 4; j++) c[i][j] = ffma2(a2, bb[j], c[i][j]);
            }
        }
        __syncthreads();
    }

#pragma unroll
    for (int i = 0; i < 8; i++) {
        float2 v0 = unpack2(c[i][0]);
        float2 v1 = unpack2(c[i][1]);
        float2 v2 = unpack2(c[i][2]);
        float2 v3 = unpack2(c[i][3]);
        float* op = g_ybuf + (size_t)(m0 + ty * 8 + i) * HDIM + n0 + tx * 8;
        *(float4*)op = make_float4(v0.x, v0.y, v1.x, v1.y);
        *(float4*)(op + 4) = make_float4(v2.x, v2.y, v3.x, v3.y);
    }
}

// ---------------------------------------------------------------------------
// Kernel 6: combine — out[t] = w0 * ybuf[p0] + w1 * ybuf[p1]
// ---------------------------------------------------------------------------
__global__ void combine_kernel(float* __restrict__ out) {
    int t = blockIdx.x;
    int j = threadIdx.x * 4;
    int p0 = g_tok_pair[2 * t], p1 = g_tok_pair[2 * t + 1];
    float w0 = g_tok_w[2 * t], w1 = g_tok_w[2 * t + 1];
    float4 y0 = *(const float4*)(g_ybuf + (size_t)p0 * HDIM + j);
    float4 y1 = *(const float4*)(g_ybuf + (size_t)p1 * HDIM + j);
    float4 r;
    r.x = w0 * y0.x + w1 * y1.x;
    r.y = w0 * y0.y + w1 * y1.y;
    r.z = w0 * y0.z + w1 * y1.z;
    r.w = w0 * y0.w + w1 * y1.w;
    *(float4*)(out + (size_t)t * HDIM + j) = r;
}

// ---------------------------------------------------------------------------
// Launch
// ---------------------------------------------------------------------------
extern "C" void kernel_launch(void* const* d_in, const int* in_sizes, int n_in,
                              void* d_out, int out_size) {
    const float* x  = (const float*)d_in[0];
    const float* gw = (const float*)d_in[1];
    const float* w1 = (const float*)d_in[2];
    const float* w2 = (const float*)d_in[3];
    float* out = (float*)d_out;

    // tuple output (out, logits): logits live after the NT*HDIM out block
    int write_logits = (out_size >= NT * HDIM + NT * NE) ? 1 : 0;

    reset_kernel<<<(MAXPAIR + 255) / 256, 256>>>();
    router_kernel<<<NT / 8, 256>>>(x, gw, out + (size_t)NT * HDIM, write_logits);
    scan_kernel<<<1, 1>>>();
    assign_kernel<<<(NT * TOPK + 255) / 256, 256>>>();
    ffn1_kernel<<<dim3(FDIM / BN, MTILES), 256>>>(x, w1);
    ffn2_kernel<<<dim3(HDIM / BN, MTILES), 256>>>(w2);
    combine_kernel<<<NT, 256>>>(out);
}

// round 9
// speedup vs baseline: 2.2894x; 2.2894x over previous
#include <cuda_runtime.h>
#include <math.h>
#include <stdint.h>

// Shapes (fixed by reference)
#define NT    8192
#define HDIM  1024
#define FDIM  4096
#define NE    8
#define TOPK  2

// GEMM tiling: block 128x128, 4 warps (64x64 each), k-chunk 16, 2 stages
#define BM 128
#define BN 128
#define KC 16
#define ASTR 20          // As row stride (floats): read bank (m*20+k)%32 conflict-free
#define BSTR 132         // Bs row stride (floats): read bank (k*132+n)%32 conflict-free
#define STAGE_FLOATS (BM * ASTR + KC * BSTR)   // 2560 + 2112 = 4672
#define ABYTES (BM * ASTR * 4)                 // 10240
#define STAGE_BYTES (STAGE_FLOATS * 4)         // 18688
// total static smem: 2 * 18688 = 37376 B  (< 48KB: no opt-in needed)

#define MAXPAIR (NT * TOPK + NE * BM)   // 17408
#define MTILES  (MAXPAIR / BM)          // 136

// ---------------------------------------------------------------------------
// Scratch (static device memory — referenced ONLY from device code; passing
// these symbols as host-side kernel args was the R7/R8 all-zeros bug: host
// shadow address + GB300 ATS silently redirected all GEMM traffic to host RAM)
// ---------------------------------------------------------------------------
__device__ int   g_counts[NE];
__device__ int   g_cursor[NE];
__device__ int   g_seg[NE + 1];
__device__ int   g_pair_token[MAXPAIR];
__device__ int   g_tok_e[NT * TOPK];
__device__ float g_tok_w[NT * TOPK];
__device__ int   g_tok_pair[NT * TOPK];
__device__ float g_zrow[HDIM];                     // never written: stays zero
__device__ float g_hbuf[(size_t)MAXPAIR * FDIM];   // relu(x@w1) raw f32
__device__ float g_ybuf[(size_t)MAXPAIR * HDIM];   // per-pair expert output

// ---------------------------------------------------------------------------
// PTX helpers (all non-arch-specific: legal on compute_103)
// ---------------------------------------------------------------------------
__device__ __forceinline__ uint32_t smem_u32(const void* p) {
    uint32_t a;
    asm("{ .reg .u64 t; cvta.to.shared.u64 t, %1; cvt.u32.u64 %0, t; }"
        : "=r"(a) : "l"(p));
    return a;
}
__device__ __forceinline__ uint32_t f2tf(float x) {   // round-to-nearest tf32
    uint32_t u;
    asm("cvt.rna.tf32.f32 %0, %1;" : "=r"(u) : "f"(x));
    return u;
}
__device__ __forceinline__ void cp16(uint32_t s, const float* g) {
    asm volatile("cp.async.cg.shared.global [%0], [%1], 16;"
                 :: "r"(s), "l"(g) : "memory");
}
__device__ __forceinline__ void cp_commit() {
    asm volatile("cp.async.commit_group;" ::: "memory");
}
__device__ __forceinline__ void cp_wait1() {
    asm volatile("cp.async.wait_group 1;" ::: "memory");
}
__device__ __forceinline__ void cp_wait0() {
    asm volatile("cp.async.wait_group 0;" ::: "memory");
}
__device__ __forceinline__ void mma_tf32(float* c, const uint32_t* a,
                                         const uint32_t* b) {
    asm volatile(
        "mma.sync.aligned.m16n8k8.row.col.f32.tf32.tf32.f32 "
        "{%0,%1,%2,%3}, {%4,%5,%6,%7}, {%8,%9}, {%0,%1,%2,%3};"
        : "+f"(c[0]), "+f"(c[1]), "+f"(c[2]), "+f"(c[3])
        : "r"(a[0]), "r"(a[1]), "r"(a[2]), "r"(a[3]), "r"(b[0]), "r"(b[1]));
}

// ---------------------------------------------------------------------------
// Kernel 0: reset per-launch state (graph replays reuse globals)
// ---------------------------------------------------------------------------
__global__ void reset_kernel() {
    int id = blockIdx.x * blockDim.x + threadIdx.x;
    if (id < MAXPAIR) g_pair_token[id] = -1;
    if (id < NE) { g_counts[id] = 0; g_cursor[id] = 0; }
}

// ---------------------------------------------------------------------------
// Kernel 1: router — exact fp32 logits + top-2 (proven in R5)
// ---------------------------------------------------------------------------
__global__ void router_kernel(const float* __restrict__ x,
                              const float* __restrict__ gw,
                              float* __restrict__ logits_out,
                              int write_logits) {
    __shared__ float gwT[NE][HDIM];
    int tid = threadIdx.x;
    for (int idx = tid; idx < HDIM * NE; idx += 256) {
        int h = idx >> 3, e = idx & 7;
        gwT[e][h] = gw[idx];
    }
    __syncthreads();

    int warp = tid >> 5, lane = tid & 31;
    int t = blockIdx.x * 8 + warp;

    float acc[NE];
#pragma unroll
    for (int e = 0; e < NE; e++) acc[e] = 0.f;
    const float* xr = x + (size_t)t * HDIM;
    for (int i = lane; i < HDIM; i += 32) {
        float xv = xr[i];
#pragma unroll
        for (int e = 0; e < NE; e++) acc[e] += xv * gwT[e][i];
    }
#pragma unroll
    for (int e = 0; e < NE; e++)
        for (int off = 16; off; off >>= 1)
            acc[e] += __shfl_down_sync(0xffffffffu, acc[e], off);

    if (lane == 0) {
        if (write_logits) {
#pragma unroll
            for (int e = 0; e < NE; e++) logits_out[t * NE + e] = acc[e];
        }
        float l1 = -INFINITY, l2 = -INFINITY;
        int i1 = 0, i2 = 0;
#pragma unroll
        for (int e = 0; e < NE; e++) {
            float v = acc[e];
            if (v > l1)      { l2 = l1; i2 = i1; l1 = v; i1 = e; }
            else if (v > l2) { l2 = v; i2 = e; }
        }
        float b = expf(l2 - l1);
        float s = 1.f + b;
        g_tok_e[2 * t] = i1;  g_tok_e[2 * t + 1] = i2;
        g_tok_w[2 * t] = 1.f / s;
        g_tok_w[2 * t + 1] = b / s;
        atomicAdd(&g_counts[i1], 1);
        atomicAdd(&g_counts[i2], 1);
    }
}

// ---------------------------------------------------------------------------
// Kernel 2/3: segment scan (pad to BM) + pair assignment
// ---------------------------------------------------------------------------
__global__ void scan_kernel() {
    int s = 0;
    for (int e = 0; e < NE; e++) {
        g_seg[e] = s;
        s += ((g_counts[e] + BM - 1) / BM) * BM;
    }
    g_seg[NE] = s;
}

__global__ void assign_kernel() {
    int id = blockIdx.x * blockDim.x + threadIdx.x;
    if (id >= NT * TOPK) return;
    int e = g_tok_e[id];
    int pos = atomicAdd(&g_cursor[e], 1);
    int p = g_seg[e] + pos;
    g_pair_token[p] = id >> 1;
    g_tok_pair[id] = p;
}

// ---------------------------------------------------------------------------
// Kernel 4: tf32 mma.sync GEMM.
//   PHASE1 (GATHER=1): A = x rows via g_pair_token, B = w1[e], Out = g_hbuf (+relu)
//   PHASE2 (GATHER=0): A = g_hbuf,                 B = w2[e], Out = g_ybuf
//   Scratch pointers resolved in DEVICE code (g_hbuf/g_ybuf), never host args.
// ---------------------------------------------------------------------------
template <int GATHER, int RELU>
__global__ __launch_bounds__(128)
void moe_mma_kernel(const float* __restrict__ Xarg,
                    const float* __restrict__ B, int K, int ldN) {
    __shared__ float smf[2 * STAGE_FLOATS];

    const float* Abase = GATHER ? Xarg : g_hbuf;   // device-side resolution
    float* Out         = GATHER ? g_hbuf : g_ybuf;

    int m0 = blockIdx.y * BM;
    if (m0 >= g_seg[NE]) return;
    int n0 = blockIdx.x * BN;

    int e = 0;
#pragma unroll
    for (int i = 1; i < NE; i++) if (m0 >= g_seg[i]) e = i;
    const float* Bexp = B + (size_t)e * K * ldN;

    int tid = threadIdx.x;
    int warp = tid >> 5, lane = tid & 31;

    // ---- load mapping:
    //  A: thread t owns row t, k 0..15  (4 x 16B)
    //  B: thread t owns k-row t>>3, cols (t&7)*16 .. +15  (4 x 16B)
    const float* aG;
    if (GATHER) {
        int tk = g_pair_token[m0 + tid];
        aG = (tk >= 0) ? (Abase + (size_t)tk * K) : g_zrow;
    } else {
        aG = Abase + (size_t)(m0 + tid) * K;
    }
    const float* bG = Bexp + (size_t)(tid >> 3) * ldN + n0 + (tid & 7) * 16;

    uint32_t sbase = smem_u32(smf);
    uint32_t aS = sbase + (uint32_t)(tid * ASTR) * 4u;
    uint32_t bS = sbase + (uint32_t)ABYTES +
                  (uint32_t)((tid >> 3) * BSTR) * 4u + (uint32_t)((tid & 7) * 64);

    const int NC = K / KC;

    float c[4][8][4];
#pragma unroll
    for (int ti = 0; ti < 4; ti++)
#pragma unroll
        for (int tj = 0; tj < 8; tj++)
#pragma unroll
            for (int q = 0; q < 4; q++) c[ti][tj][q] = 0.f;

    int amBase = (warp >> 1) * 64 + (lane >> 2);
    int bnBase = (warp & 1) * 64 + (lane >> 2);
    int kl = lane & 3;

    // ---- prologue: chunk 0
#pragma unroll
    for (int j = 0; j < 4; j++) cp16(aS + j * 16, aG + j * 4);
#pragma unroll
    for (int j = 0; j < 4; j++) cp16(bS + j * 16, bG + j * 4);
    cp_commit();

    for (int i = 0; i < NC; i++) {
        if (i + 1 < NC) {
            uint32_t so = (uint32_t)(((i + 1) & 1) * STAGE_BYTES);
            size_t ko = (size_t)(i + 1) * KC;
#pragma unroll
            for (int j = 0; j < 4; j++) cp16(aS + so + j * 16, aG + ko + j * 4);
#pragma unroll
            for (int j = 0; j < 4; j++) cp16(bS + so + j * 16, bG + ko * ldN + j * 4);
            cp_commit();
            cp_wait1();
        } else {
            cp_wait0();
        }
        __syncthreads();

        const float* As = smf + (i & 1) * STAGE_FLOATS;
        const float* Bs = As + BM * ASTR;

#pragma unroll
        for (int s = 0; s < KC / 8; s++) {
            int k0 = s * 8 + kl;
            uint32_t a[4][4], b[8][2];
#pragma unroll
            for (int ti = 0; ti < 4; ti++) {
                int m = amBase + ti * 16;
                a[ti][0] = f2tf(As[m * ASTR + k0]);
                a[ti][1] = f2tf(As[(m + 8) * ASTR + k0]);
                a[ti][2] = f2tf(As[m * ASTR + k0 + 4]);
                a[ti][3] = f2tf(As[(m + 8) * ASTR + k0 + 4]);
            }
#pragma unroll
            for (int tj = 0; tj < 8; tj++) {
                int n = bnBase + tj * 8;
                b[tj][0] = f2tf(Bs[k0 * BSTR + n]);
                b[tj][1] = f2tf(Bs[(k0 + 4) * BSTR + n]);
            }
#pragma unroll
            for (int ti = 0; ti < 4; ti++)
#pragma unroll
                for (int tj = 0; tj < 8; tj++)
                    mma_tf32(c[ti][tj], a[ti], b[tj]);
        }
        __syncthreads();
    }

    // ---- epilogue: write C fragments (optionally relu) straight to gmem
    int cm = m0 + (warp >> 1) * 64 + (lane >> 2);
    int cn = n0 + (warp & 1) * 64 + (lane & 3) * 2;
#pragma unroll
    for (int ti = 0; ti < 4; ti++) {
#pragma unroll
        for (int tj = 0; tj < 8; tj++) {
            float v0 = c[ti][tj][0], v1 = c[ti][tj][1];
            float v2 = c[ti][tj][2], v3 = c[ti][tj][3];
            if (RELU) {
                v0 = fmaxf(v0, 0.f); v1 = fmaxf(v1, 0.f);
                v2 = fmaxf(v2, 0.f); v3 = fmaxf(v3, 0.f);
            }
            size_t r0 = (size_t)(cm + ti * 16) * ldN + cn + tj * 8;
            size_t r1 = (size_t)(cm + ti * 16 + 8) * ldN + cn + tj * 8;
            *(float2*)(Out + r0) = make_float2(v0, v1);
            *(float2*)(Out + r1) = make_float2(v2, v3);
        }
    }
}

// ---------------------------------------------------------------------------
// Kernel 5: combine — out[t] = w0 * ybuf[p0] + w1 * ybuf[p1]
// ---------------------------------------------------------------------------
__global__ void combine_kernel(float* __restrict__ out) {
    int t = blockIdx.x;
    int j = threadIdx.x * 4;
    int p0 = g_tok_pair[2 * t], p1 = g_tok_pair[2 * t + 1];
    float w0 = g_tok_w[2 * t], w1 = g_tok_w[2 * t + 1];
    float4 y0 = *(const float4*)(g_ybuf + (size_t)p0 * HDIM + j);
    float4 y1 = *(const float4*)(g_ybuf + (size_t)p1 * HDIM + j);
    float4 r;
    r.x = w0 * y0.x + w1 * y1.x;
    r.y = w0 * y0.y + w1 * y1.y;
    r.z = w0 * y0.z + w1 * y1.z;
    r.w = w0 * y0.w + w1 * y1.w;
    *(float4*)(out + (size_t)t * HDIM + j) = r;
}

// ---------------------------------------------------------------------------
// Launch — only harness pointers cross the host/device boundary
// ---------------------------------------------------------------------------
extern "C" void kernel_launch(void* const* d_in, const int* in_sizes, int n_in,
                              void* d_out, int out_size) {
    const float* x  = (const float*)d_in[0];
    const float* gw = (const float*)d_in[1];
    const float* w1 = (const float*)d_in[2];
    const float* w2 = (const float*)d_in[3];
    float* out = (float*)d_out;

    int write_logits = (out_size >= NT * HDIM + NT * NE) ? 1 : 0;

    reset_kernel<<<(MAXPAIR + 255) / 256, 256>>>();
    router_kernel<<<NT / 8, 256>>>(x, gw, out + (size_t)NT * HDIM, write_logits);
    scan_kernel<<<1, 1>>>();
    assign_kernel<<<(NT * TOPK + 255) / 256, 256>>>();
    // GEMM1: g_hbuf[p,:F] = relu(x[tok(p),:H] @ w1[e])   (K=H, ldN=F)
    moe_mma_kernel<1, 1><<<dim3(FDIM / BN, MTILES), 128>>>(x, w1, HDIM, FDIM);
    // GEMM2: g_ybuf[p,:H] = g_hbuf[p,:F] @ w2[e]         (K=F, ldN=H)
    moe_mma_kernel<0, 0><<<dim3(HDIM / BN, MTILES), 128>>>(x, w2, FDIM, HDIM);
    combine_kernel<<<NT, 256>>>(out);
}